// round 3
// baseline (speedup 1.0000x reference)
#include <cuda_runtime.h>
#include <math.h>

#define S 48
#define BATCH 16
#define HID 512
#define HDIR 256
#define NL 16
#define M_ROWS 768            // S*BATCH
#define VOUT 32000

// ---------------- device scratch (static, no allocation) ----------------
__device__ float g_act0[M_ROWS * HID];
__device__ float g_act1[M_ROWS * HID];
__device__ float g_G[M_ROWS * 2048];
__device__ float g_hping[8192];
__device__ float g_hpong[8192];
__device__ float g_dech0[NL * 8192];
__device__ float g_decc0[NL * 8192];
__device__ unsigned g_cnt = 0;
__device__ unsigned g_gen = 0;

// ---------------- software grid barrier (all CTAs co-resident) ----------------
__device__ __forceinline__ void grid_bar(unsigned& lgen, unsigned nb) {
    __syncthreads();
    if (threadIdx.x == 0) {
        __threadfence();
        unsigned old = atomicAdd(&g_cnt, 1u);
        if (old == nb - 1u) {
            atomicExch(&g_cnt, 0u);
            __threadfence();
            atomicExch(&g_gen, lgen + 1u);
        } else {
            while (*(volatile unsigned*)&g_gen != lgen + 1u) { __nanosleep(32); }
        }
        __threadfence();
        lgen += 1u;
    }
    __syncthreads();
}

// ---------------- embedding gather ----------------
__global__ void embed_k(const float* __restrict__ emb, const int* __restrict__ ids,
                        float* __restrict__ out) {
    int tb = blockIdx.x;            // t*16+b
    int t = tb >> 4, b = tb & 15;
    int id = ids[b * S + t];
    const float4* src = reinterpret_cast<const float4*>(emb) + (size_t)id * (HID / 4);
    float4* dst = reinterpret_cast<float4*>(out) + (size_t)tb * (HID / 4);
    dst[threadIdx.x] = src[threadIdx.x];
}

// ---------------- C[m][n] = A[m][:512] . W[n][:512] + bias[n], M=768, K=512 ----------------
__global__ __launch_bounds__(256) void gemm_k(
    const float* __restrict__ A, const float* __restrict__ W,
    const float* __restrict__ bias, float* __restrict__ C,
    size_t sB, size_t sT, size_t sN) {
    __shared__ float4 smem4[(16 * 68 * 2) / 4];
    float* As = (float*)smem4;
    float* Ws = As + 16 * 68;
    int tid = threadIdx.x;
    int tx = tid & 15, ty = tid >> 4;
    int n0 = blockIdx.x * 64, m0 = blockIdx.y * 64;
    int r = tid >> 2, kq = (tid & 3) * 4;

    float acc[16];
#pragma unroll
    for (int i = 0; i < 16; ++i) acc[i] = 0.f;

    for (int k0 = 0; k0 < 512; k0 += 16) {
        float4 a = *reinterpret_cast<const float4*>(A + (size_t)(m0 + r) * 512 + k0 + kq);
        float4 w = *reinterpret_cast<const float4*>(W + (size_t)(n0 + r) * 512 + k0 + kq);
        As[(kq + 0) * 68 + r] = a.x; As[(kq + 1) * 68 + r] = a.y;
        As[(kq + 2) * 68 + r] = a.z; As[(kq + 3) * 68 + r] = a.w;
        Ws[(kq + 0) * 68 + r] = w.x; Ws[(kq + 1) * 68 + r] = w.y;
        Ws[(kq + 2) * 68 + r] = w.z; Ws[(kq + 3) * 68 + r] = w.w;
        __syncthreads();
#pragma unroll
        for (int kk = 0; kk < 16; ++kk) {
            float4 av = *reinterpret_cast<const float4*>(&As[kk * 68 + ty * 4]);
            float4 wv = *reinterpret_cast<const float4*>(&Ws[kk * 68 + tx * 4]);
            acc[0]  += av.x * wv.x; acc[1]  += av.x * wv.y; acc[2]  += av.x * wv.z; acc[3]  += av.x * wv.w;
            acc[4]  += av.y * wv.x; acc[5]  += av.y * wv.y; acc[6]  += av.y * wv.z; acc[7]  += av.y * wv.w;
            acc[8]  += av.z * wv.x; acc[9]  += av.z * wv.y; acc[10] += av.z * wv.z; acc[11] += av.z * wv.w;
            acc[12] += av.w * wv.x; acc[13] += av.w * wv.y; acc[14] += av.w * wv.z; acc[15] += av.w * wv.w;
        }
        __syncthreads();
    }
#pragma unroll
    for (int i = 0; i < 4; ++i) {
        int m = m0 + ty * 4 + i;
        int b = m & 15, t = m >> 4;
#pragma unroll
        for (int jx = 0; jx < 4; ++jx) {
            int n = n0 + tx * 4 + jx;
            C[(size_t)b * sB + (size_t)t * sT + (size_t)n * sN] = acc[i * 4 + jx] + bias[n];
        }
    }
}

__device__ __forceinline__ float sigm(float x) { return 1.f / (1.f + expf(-x)); }

// ---------------- persistent encoder layer: 48 steps, both directions ----------------
// grid 128: bx>>6 = dir, bx&63 = j-block (4 j). block 128 = 4 j x 32 k-chunks
__global__ __launch_bounds__(128, 1) void enc_layer_k(
    const float* __restrict__ Whh,             // (2,1024,256)
    const float* __restrict__ G, float* __restrict__ xs_out,
    float* __restrict__ hp, float* __restrict__ hq,
    float* __restrict__ dh, float* __restrict__ dc) {
    __shared__ float4 sm4[2112];
    __shared__ float redout[256];
    __shared__ float c_sm[64];
    float* sm = (float*)sm4;
    int tid = threadIdx.x;
    int ty = tid >> 5, kc = tid & 31;
    int dir = blockIdx.x >> 6;
    int jb = blockIdx.x & 63;
    int j0 = jb * 4;
    int j = j0 + ty;

    // preload recurrent weights into registers (held across all 48 steps)
    const float4* w4 = reinterpret_cast<const float4*>(Whh + (size_t)dir * 1024 * 256);
    float4 wr[2][4];
#pragma unroll
    for (int it = 0; it < 2; ++it) {
        int k4 = it * 32 + kc;
        wr[it][0] = w4[(size_t)(0 * 256 + j) * 64 + k4];
        wr[it][1] = w4[(size_t)(1 * 256 + j) * 64 + k4];
        wr[it][2] = w4[(size_t)(2 * 256 + j) * 64 + k4];
        wr[it][3] = w4[(size_t)(3 * 256 + j) * 64 + k4];
    }
    // init h=0 (our 64-value slice), c=0
    if (tid < 64) {
        int jj = tid >> 4, b = tid & 15;
        hp[dir * 4096 + b * 256 + j0 + jj] = 0.f;
        c_sm[tid] = 0.f;
    }
    unsigned lgen = 0;
    if (tid == 0) lgen = *(volatile unsigned*)&g_gen;
    grid_bar(lgen, 128);

    for (int t = 0; t < 48; ++t) {
        const float* h_in = (t & 1) ? hq : hp;
        float* h_out = (t & 1) ? hp : hq;
        const float4* hin4 = reinterpret_cast<const float4*>(h_in + dir * 4096);
#pragma unroll
        for (int i = 0; i < 8; ++i) sm4[tid + i * 128] = hin4[tid + i * 128];
        __syncthreads();

        float acc[64];
#pragma unroll
        for (int i = 0; i < 64; ++i) acc[i] = 0.f;
#pragma unroll
        for (int it = 0; it < 2; ++it) {
            int k4 = it * 32 + kc;
#pragma unroll
            for (int b = 0; b < 16; ++b) {
                float4 hv = sm4[b * 64 + k4];
                acc[0 * 16 + b] += wr[it][0].x * hv.x + wr[it][0].y * hv.y + wr[it][0].z * hv.z + wr[it][0].w * hv.w;
                acc[1 * 16 + b] += wr[it][1].x * hv.x + wr[it][1].y * hv.y + wr[it][1].z * hv.z + wr[it][1].w * hv.w;
                acc[2 * 16 + b] += wr[it][2].x * hv.x + wr[it][2].y * hv.y + wr[it][2].z * hv.z + wr[it][2].w * hv.w;
                acc[3 * 16 + b] += wr[it][3].x * hv.x + wr[it][3].y * hv.y + wr[it][3].z * hv.z + wr[it][3].w * hv.w;
            }
        }
        __syncthreads();
#pragma unroll
        for (int g = 0; g < 4; ++g)
#pragma unroll
            for (int b = 0; b < 16; ++b)
                sm[((ty * 4 + g) * 16 + b) * 33 + kc] = acc[g * 16 + b];
        __syncthreads();
#pragma unroll
        for (int rr = 0; rr < 2; ++rr) {
            int o = tid + rr * 128;
            float s = 0.f;
#pragma unroll
            for (int q = 0; q < 32; ++q) s += sm[o * 33 + q];
            redout[o] = s;
        }
        __syncthreads();
        if (tid < 64) {
            int jj = tid >> 4, b = tid & 15;
            int jg = j0 + jj;
            int tt = dir ? (47 - t) : t;
            size_t gb = (size_t)(tt * 16 + b) * 2048 + (size_t)dir * 1024;
            float ip = redout[(jj * 4 + 0) * 16 + b] + G[gb + 0 * 256 + jg];
            float fp = redout[(jj * 4 + 1) * 16 + b] + G[gb + 1 * 256 + jg];
            float gp = redout[(jj * 4 + 2) * 16 + b] + G[gb + 2 * 256 + jg];
            float op = redout[(jj * 4 + 3) * 16 + b] + G[gb + 3 * 256 + jg];
            float c = sigm(fp) * c_sm[tid] + sigm(ip) * tanhf(gp);
            c_sm[tid] = c;
            float h = sigm(op) * tanhf(c);
            h_out[dir * 4096 + b * 256 + jg] = h;
            xs_out[(size_t)(tt * 16 + b) * 512 + dir * 256 + jg] = h;
            if (t == 47) {                       // final states -> decoder init layout
                dh[b * 512 + dir * 256 + jg] = h;
                dc[b * 512 + dir * 256 + jg] = c;
            }
        }
        grid_bar(lgen, 128);
    }
}

// ---------------- persistent decoder layer: 48 steps ----------------
// grid 128 (4 j each), block 128 = 4 j-lanes x 32 k-chunks
__global__ __launch_bounds__(128, 1) void dec_layer_k(
    const float* __restrict__ Whh,             // (2048,512)
    const float* __restrict__ G, float* __restrict__ ds_out,
    float* __restrict__ hp, float* __restrict__ hq,
    const float* __restrict__ dh, const float* __restrict__ dc) {
    __shared__ float4 sm4[2112];
    __shared__ float redout[256];
    __shared__ float c_sm[64];
    float* sm = (float*)sm4;
    int tid = threadIdx.x;
    int ty = tid >> 5, kc = tid & 31;
    int j0 = blockIdx.x * 4;
    int j = j0 + ty;

    const float4* w4 = reinterpret_cast<const float4*>(Whh);
    float4 wr[4][4];
#pragma unroll
    for (int it = 0; it < 4; ++it) {
        int k4 = it * 32 + kc;
        wr[it][0] = w4[(size_t)(0 * 512 + j) * 128 + k4];
        wr[it][1] = w4[(size_t)(1 * 512 + j) * 128 + k4];
        wr[it][2] = w4[(size_t)(2 * 512 + j) * 128 + k4];
        wr[it][3] = w4[(size_t)(3 * 512 + j) * 128 + k4];
    }
    if (tid < 64) {
        int jj = tid >> 4, b = tid & 15;
        int jg = j0 + jj;
        hp[b * 512 + jg] = dh[b * 512 + jg];
        c_sm[tid] = dc[b * 512 + jg];
    }
    unsigned lgen = 0;
    if (tid == 0) lgen = *(volatile unsigned*)&g_gen;
    grid_bar(lgen, 128);

    for (int t = 0; t < 48; ++t) {
        const float* h_in = (t & 1) ? hq : hp;
        float* h_out = (t & 1) ? hp : hq;
        const float4* hin4 = reinterpret_cast<const float4*>(h_in);
#pragma unroll
        for (int i = 0; i < 16; ++i) sm4[tid + i * 128] = hin4[tid + i * 128];
        __syncthreads();

        float acc[64];
#pragma unroll
        for (int i = 0; i < 64; ++i) acc[i] = 0.f;
#pragma unroll
        for (int it = 0; it < 4; ++it) {
            int k4 = it * 32 + kc;
#pragma unroll
            for (int b = 0; b < 16; ++b) {
                float4 hv = sm4[b * 128 + k4];
                acc[0 * 16 + b] += wr[it][0].x * hv.x + wr[it][0].y * hv.y + wr[it][0].z * hv.z + wr[it][0].w * hv.w;
                acc[1 * 16 + b] += wr[it][1].x * hv.x + wr[it][1].y * hv.y + wr[it][1].z * hv.z + wr[it][1].w * hv.w;
                acc[2 * 16 + b] += wr[it][2].x * hv.x + wr[it][2].y * hv.y + wr[it][2].z * hv.z + wr[it][2].w * hv.w;
                acc[3 * 16 + b] += wr[it][3].x * hv.x + wr[it][3].y * hv.y + wr[it][3].z * hv.z + wr[it][3].w * hv.w;
            }
        }
        __syncthreads();
#pragma unroll
        for (int g = 0; g < 4; ++g)
#pragma unroll
            for (int b = 0; b < 16; ++b)
                sm[((ty * 4 + g) * 16 + b) * 33 + kc] = acc[g * 16 + b];
        __syncthreads();
#pragma unroll
        for (int rr = 0; rr < 2; ++rr) {
            int o = tid + rr * 128;
            float s = 0.f;
#pragma unroll
            for (int q = 0; q < 32; ++q) s += sm[o * 33 + q];
            redout[o] = s;
        }
        __syncthreads();
        if (tid < 64) {
            int jj = tid >> 4, b = tid & 15;
            int jg = j0 + jj;
            size_t gb = (size_t)(t * 16 + b) * 2048;
            float ip = redout[(jj * 4 + 0) * 16 + b] + G[gb + 0 * 512 + jg];
            float fp = redout[(jj * 4 + 1) * 16 + b] + G[gb + 1 * 512 + jg];
            float gp = redout[(jj * 4 + 2) * 16 + b] + G[gb + 2 * 512 + jg];
            float op = redout[(jj * 4 + 3) * 16 + b] + G[gb + 3 * 512 + jg];
            float c = sigm(fp) * c_sm[tid] + sigm(ip) * tanhf(gp);
            c_sm[tid] = c;
            float h = sigm(op) * tanhf(c);
            h_out[b * 512 + jg] = h;
            ds_out[(size_t)(t * 16 + b) * 512 + jg] = h;
        }
        grid_bar(lgen, 128);
    }
}

// ---------------- launch sequence ----------------
extern "C" void kernel_launch(void* const* d_in, const int* in_sizes, int n_in,
                              void* d_out, int out_size) {
    const int*   x        = (const int*)d_in[0];
    const int*   y        = (const int*)d_in[1];
    const float* enc_emb  = (const float*)d_in[2];
    const float* enc_Wih  = (const float*)d_in[3];
    const float* enc_Whh  = (const float*)d_in[4];
    const float* enc_b    = (const float*)d_in[5];
    const float* dec_emb  = (const float*)d_in[6];
    const float* dec_Wih  = (const float*)d_in[7];
    const float* dec_Whh  = (const float*)d_in[8];
    const float* dec_b    = (const float*)d_in[9];
    const float* lin_W    = (const float*)d_in[10];
    const float* lin_b    = (const float*)d_in[11];
    float* out = (float*)d_out;

    float *act0, *act1, *G, *hp, *hq, *dh, *dc;
    cudaGetSymbolAddress((void**)&act0, g_act0);
    cudaGetSymbolAddress((void**)&act1, g_act1);
    cudaGetSymbolAddress((void**)&G,    g_G);
    cudaGetSymbolAddress((void**)&hp,   g_hping);
    cudaGetSymbolAddress((void**)&hq,   g_hpong);
    cudaGetSymbolAddress((void**)&dh,   g_dech0);
    cudaGetSymbolAddress((void**)&dc,   g_decc0);
    float* bufs[2] = {act0, act1};

    // ---- encoder ----
    embed_k<<<768, 128>>>(enc_emb, x, bufs[0]);
    int p = 0;
    for (int l = 0; l < NL; ++l) {
        gemm_k<<<dim3(32, 12), 256>>>(bufs[p], enc_Wih + (size_t)l * 1024 * 1024,
                                      enc_b + l * 2048, G,
                                      (size_t)2048, (size_t)32768, (size_t)1);
        enc_layer_k<<<128, 128>>>(enc_Whh + (size_t)l * 2 * 1024 * 256, G,
                                  bufs[1 - p], hp, hq,
                                  dh + l * 8192, dc + l * 8192);
        p ^= 1;
    }

    // ---- decoder ----
    embed_k<<<768, 128>>>(dec_emb, y, bufs[p]);
    for (int l = 0; l < NL; ++l) {
        gemm_k<<<dim3(32, 12), 256>>>(bufs[p], dec_Wih + (size_t)l * 2048 * 512,
                                      dec_b + l * 2048, G,
                                      (size_t)2048, (size_t)32768, (size_t)1);
        dec_layer_k<<<128, 128>>>(dec_Whh + (size_t)l * 2048 * 512, G,
                                  bufs[1 - p], hp, hq,
                                  dh + l * 8192, dc + l * 8192);
        p ^= 1;
    }

    // ---- final projection: out[b][v][t] ----
    gemm_k<<<dim3(500, 12), 256>>>(bufs[p], lin_W, lin_b, out,
                                   (size_t)VOUT * 48, (size_t)1, (size_t)48);
}